// round 6
// baseline (speedup 1.0000x reference)
#include <cuda_runtime.h>
#include <math.h>
#include <stdint.h>

// Problem constants
#define BB_  4
#define SS_  8192
#define EE_  1024
#define HH_  16
#define DD_  64
#define SP_  512
#define MQKV (BB_*SS_)
#define MOUT (BB_*SP_)

// Scratch
__device__ float g_q[BB_*HH_*SP_*DD_];     // [B,H,S',D]
__device__ float g_k[BB_*HH_*SP_*DD_];
__device__ float g_v[BB_*HH_*SP_*DD_];
__device__ float g_ctx[BB_*SP_*EE_];       // [B,S',E]

// ---------------------------------------------------------------------------
// helpers
// ---------------------------------------------------------------------------
__device__ __forceinline__ uint32_t f2tf32(float f) {
    uint32_t u;
    asm("cvt.rna.tf32.f32 %0, %1;" : "=r"(u) : "f"(f));
    return u;
}

__device__ __forceinline__ void mma_tf32(float c[4], const uint32_t a[4], const uint32_t b[2]) {
    asm volatile(
        "mma.sync.aligned.m16n8k8.row.col.f32.tf32.tf32.f32 "
        "{%0,%1,%2,%3}, {%4,%5,%6,%7}, {%8,%9}, {%0,%1,%2,%3};\n"
        : "+f"(c[0]), "+f"(c[1]), "+f"(c[2]), "+f"(c[3])
        : "r"(a[0]), "r"(a[1]), "r"(a[2]), "r"(a[3]), "r"(b[0]), "r"(b[1]));
}

// Fragment-ordered smem:
//  A element (m, k) in a 128x16 tile: s=k/8, mtile=m/16,
//    lane=(m%8)*4+(k%4), reg=(m%16)/8 + 2*((k%8)/4)
//    offset = (s*8 + mtile)*128 + lane*4 + reg
//  B element (n, k) in a BNx16 tile:  s=k/8, n8=n/8, p=n8/2, q=n8%2,
//    lane=(n%8)*4+(k%4), reg=(k%8)/4
//    offset = (s*NP + p)*128 + lane*4 + q*2 + reg
// A warp's MMA operands are then single conflict-free LDS.128s.

#define QKV_ASZ (2*8*128)    // 2048 u32 per stage
#define QKV_BSZ (2*12*128)   // 3072 u32 per stage (NP=12, BN=192)
#define OP_BSZ  (2*8*128)    // 2048 u32 per stage (NP=8,  BN=128)

// ---------------------------------------------------------------------------
// Kernel 1: fused QKV projection.  BM=128, BN=192, BK=16, 512 thr / 16 warps,
// warp tile 32m x 48n.  Double-buffered fragment-ordered smem (40 KB).
// ---------------------------------------------------------------------------
__global__ __launch_bounds__(512)
void qkv_mma(const float* __restrict__ x,
             const float* __restrict__ Wq, const float* __restrict__ bq,
             const float* __restrict__ Wk, const float* __restrict__ bk,
             const float* __restrict__ Wv, const float* __restrict__ bv)
{
    __shared__ uint32_t Af[2][QKV_ASZ];
    __shared__ uint32_t Bf[2][QKV_BSZ];

    const int tid  = threadIdx.x;
    const int warp = tid >> 5;
    const int lane = tid & 31;
    const int wm   = warp >> 2;          // 0..3 -> m offset wm*32
    const int wn   = warp & 3;           // 0..3 -> n offset wn*48
    const int m0   = blockIdx.x * 128;

    // --- gmem load + smem scatter assignments (fixed; only k moves) ---
    const int arow = tid >> 2;
    const int ac4  = (tid & 3) * 4;      // k offset within 16-k tile
    const float* a_src = x + (size_t)(m0 + arow) * 1024 + ac4;
    const int sK   = ac4 >> 3;
    const int regA = ((arow & 15) >> 3) + (((ac4 & 7) >> 2) << 1);
    const int a_off = (sK * 8 + (arow >> 4)) * 128 + (arow & 7) * 16 + regA;

    const int b1row = tid >> 2;          // 0..127 : Wq|Wk
    const float* b1_src = (b1row < 64 ? Wq + (size_t)b1row * 1024
                                      : Wk + (size_t)(b1row - 64) * 1024) + ac4;
    const int regB = (ac4 & 7) >> 2;
    {   }
    const int n81 = b1row >> 3;
    const int b1_off = (sK * 12 + (n81 >> 1)) * 128 + (b1row & 7) * 16 + (n81 & 1) * 2 + regB;

    const bool has2 = (tid < 256);
    const int b2row = 128 + (tid >> 2);  // 128..191 : Wv
    const float* b2_src = Wv + (size_t)(tid >> 2) * 1024 + ac4;
    const int n82 = b2row >> 3;
    const int b2_off = (sK * 12 + (n82 >> 1)) * 128 + (b2row & 7) * 16 + (n82 & 1) * 2 + regB;

    float acc[2][6][4];
    #pragma unroll
    for (int mt = 0; mt < 2; mt++)
        #pragma unroll
        for (int nt = 0; nt < 6; nt++)
            #pragma unroll
            for (int e = 0; e < 4; e++) acc[mt][nt][e] = 0.f;

    // preload k-tile 0
    float4 ra  = *(const float4*)(a_src);
    float4 rb1 = *(const float4*)(b1_src);
    float4 rb2 = has2 ? *(const float4*)(b2_src) : make_float4(0.f,0.f,0.f,0.f);

    for (int it = 0; it < 64; ++it) {
        const int st = it & 1;
        // scatter current tile into fragment order (tf32-converted once)
        Af[st][a_off     ] = f2tf32(ra.x);
        Af[st][a_off +  4] = f2tf32(ra.y);
        Af[st][a_off +  8] = f2tf32(ra.z);
        Af[st][a_off + 12] = f2tf32(ra.w);
        Bf[st][b1_off     ] = f2tf32(rb1.x);
        Bf[st][b1_off +  4] = f2tf32(rb1.y);
        Bf[st][b1_off +  8] = f2tf32(rb1.z);
        Bf[st][b1_off + 12] = f2tf32(rb1.w);
        if (has2) {
            Bf[st][b2_off     ] = f2tf32(rb2.x);
            Bf[st][b2_off +  4] = f2tf32(rb2.y);
            Bf[st][b2_off +  8] = f2tf32(rb2.z);
            Bf[st][b2_off + 12] = f2tf32(rb2.w);
        }
        __syncthreads();

        // prefetch next tile (overlaps compute)
        if (it < 63) {
            int k0 = (it + 1) * 16;
            ra  = *(const float4*)(a_src + k0);
            rb1 = *(const float4*)(b1_src + k0);
            if (has2) rb2 = *(const float4*)(b2_src + k0);
        }

        const uint32_t* Ac = Af[st];
        const uint32_t* Bc = Bf[st];
        #pragma unroll
        for (int s = 0; s < 2; s++) {
            uint4 av0 = *(const uint4*)&Ac[(s * 8 + wm * 2 + 0) * 128 + lane * 4];
            uint4 av1 = *(const uint4*)&Ac[(s * 8 + wm * 2 + 1) * 128 + lane * 4];
            uint32_t af0[4] = {av0.x, av0.y, av0.z, av0.w};
            uint32_t af1[4] = {av1.x, av1.y, av1.z, av1.w};
            #pragma unroll
            for (int p = 0; p < 3; p++) {
                uint4 bv = *(const uint4*)&Bc[(s * 12 + wn * 3 + p) * 128 + lane * 4];
                uint32_t bfe[2] = {bv.x, bv.y};
                uint32_t bfo[2] = {bv.z, bv.w};
                mma_tf32(acc[0][2*p  ], af0, bfe);
                mma_tf32(acc[1][2*p  ], af1, bfe);
                mma_tf32(acc[0][2*p+1], af0, bfo);
                mma_tf32(acc[1][2*p+1], af1, bfo);
            }
        }
        __syncthreads();
    }

    // Epilogue: bias + scatter into [B,H,S',D]
    const int lq = lane >> 2;
    const int lr = lane & 3;
    #pragma unroll
    for (int mt = 0; mt < 2; mt++) {
        #pragma unroll
        for (int half = 0; half < 2; half++) {
            int m  = m0 + wm * 32 + mt * 16 + half * 8 + lq;
            int bb = m >> 13;
            int s  = m & 8191;
            int sp = s >> 4;
            int h  = s & 15;
            size_t rowoff = ((size_t)(bb * 16 + h) * 512 + sp) * 64;
            #pragma unroll
            for (int nt = 0; nt < 6; nt++) {
                int n   = wn * 48 + nt * 8 + 2 * lr;
                int mat = n >> 6;
                int nn  = n & 63;
                float* dst = (mat == 0) ? g_q : (mat == 1 ? g_k : g_v);
                const float* bias = (mat == 0) ? bq : (mat == 1 ? bk : bv);
                float2 v;
                v.x = acc[mt][nt][half * 2 + 0] + bias[nn];
                v.y = acc[mt][nt][half * 2 + 1] + bias[nn + 1];
                *(float2*)(dst + rowoff + nn) = v;
            }
        }
    }
}

// ---------------------------------------------------------------------------
// Kernel 2: attention, TF32 mma (unchanged).
// ---------------------------------------------------------------------------
#define KSTR 68
#define VSTR 72

__global__ __launch_bounds__(256)
void attn_mma()
{
    __shared__ float Ks[64 * KSTR];
    __shared__ float Vs[64 * VSTR];

    const int bh   = blockIdx.x;
    const int qt   = blockIdx.y;
    const int tid  = threadIdx.x;
    const int warp = tid >> 5;
    const int lane = tid & 31;
    const int lq   = lane >> 2;
    const int lr   = lane & 3;

    const float* qbase = g_q + ((size_t)bh * 512 + qt * 128 + warp * 16) * 64;
    uint32_t qa[8][4];
    #pragma unroll
    for (int ks = 0; ks < 8; ks++) {
        qa[ks][0] = f2tf32(qbase[(size_t)lq       * 64 + ks * 8 + lr    ] * 0.125f);
        qa[ks][1] = f2tf32(qbase[(size_t)(lq + 8) * 64 + ks * 8 + lr    ] * 0.125f);
        qa[ks][2] = f2tf32(qbase[(size_t)lq       * 64 + ks * 8 + lr + 4] * 0.125f);
        qa[ks][3] = f2tf32(qbase[(size_t)(lq + 8) * 64 + ks * 8 + lr + 4] * 0.125f);
    }

    float o[8][4];
    #pragma unroll
    for (int nt = 0; nt < 8; nt++)
        #pragma unroll
        for (int e = 0; e < 4; e++) o[nt][e] = 0.f;
    float lsum0 = 0.f, lsum1 = 0.f;

    const float* kb = g_k + (size_t)bh * 512 * 64;
    const float* vb = g_v + (size_t)bh * 512 * 64;

    for (int kt = 0; kt < 8; kt++) {
        __syncthreads();
        #pragma unroll
        for (int i = 0; i < 4; i++) {
            int idx = tid + i * 256;
            int row = idx >> 4, c4 = (idx & 15) << 2;
            *(float4*)(Ks + row * KSTR + c4) = *(const float4*)(kb + (size_t)kt * 4096 + idx * 4);
            *(float4*)(Vs + row * VSTR + c4) = *(const float4*)(vb + (size_t)kt * 4096 + idx * 4);
        }
        __syncthreads();

        float sc[8][4];
        #pragma unroll
        for (int nt = 0; nt < 8; nt++) {
            sc[nt][0] = sc[nt][1] = sc[nt][2] = sc[nt][3] = 0.f;
            #pragma unroll
            for (int ks = 0; ks < 8; ks++) {
                uint32_t bf[2];
                bf[0] = f2tf32(Ks[(nt * 8 + lq) * KSTR + ks * 8 + lr    ]);
                bf[1] = f2tf32(Ks[(nt * 8 + lq) * KSTR + ks * 8 + lr + 4]);
                mma_tf32(sc[nt], qa[ks], bf);
            }
        }

        #pragma unroll
        for (int nt = 0; nt < 8; nt++) {
            float p0 = __expf(sc[nt][0]), p1 = __expf(sc[nt][1]);
            float p2 = __expf(sc[nt][2]), p3 = __expf(sc[nt][3]);
            sc[nt][0] = p0; sc[nt][1] = p1; sc[nt][2] = p2; sc[nt][3] = p3;
            lsum0 += p0 + p1;
            lsum1 += p2 + p3;
        }

        #pragma unroll
        for (int ks = 0; ks < 8; ks++) {
            int src  = (lane & ~3) | (lr >> 1);
            float t0 = __shfl_sync(0xffffffffu, sc[ks][0], src);
            float t1 = __shfl_sync(0xffffffffu, sc[ks][1], src);
            float t2 = __shfl_sync(0xffffffffu, sc[ks][2], src);
            float t3 = __shfl_sync(0xffffffffu, sc[ks][3], src);
            float u0 = __shfl_sync(0xffffffffu, sc[ks][0], src + 2);
            float u1 = __shfl_sync(0xffffffffu, sc[ks][1], src + 2);
            float u2 = __shfl_sync(0xffffffffu, sc[ks][2], src + 2);
            float u3 = __shfl_sync(0xffffffffu, sc[ks][3], src + 2);
            uint32_t pa[4];
            pa[0] = f2tf32((lr & 1) ? t1 : t0);
            pa[1] = f2tf32((lr & 1) ? t3 : t2);
            pa[2] = f2tf32((lr & 1) ? u1 : u0);
            pa[3] = f2tf32((lr & 1) ? u3 : u2);
            #pragma unroll
            for (int ntd = 0; ntd < 8; ntd++) {
                uint32_t bf[2];
                bf[0] = f2tf32(Vs[(ks * 8 + lr    ) * VSTR + ntd * 8 + lq]);
                bf[1] = f2tf32(Vs[(ks * 8 + lr + 4) * VSTR + ntd * 8 + lq]);
                mma_tf32(o[ntd], pa, bf);
            }
        }
    }

    lsum0 += __shfl_xor_sync(0xffffffffu, lsum0, 1);
    lsum0 += __shfl_xor_sync(0xffffffffu, lsum0, 2);
    lsum1 += __shfl_xor_sync(0xffffffffu, lsum1, 1);
    lsum1 += __shfl_xor_sync(0xffffffffu, lsum1, 2);
    const float inv0 = 1.f / lsum0;
    const float inv1 = 1.f / lsum1;

    const int bb = bh >> 4, h = bh & 15;
    const int qrow0 = qt * 128 + warp * 16 + lq;
    float* out0 = g_ctx + ((size_t)(bb * 512 + qrow0)) * 1024 + h * 64;
    float* out1 = out0 + (size_t)8 * 1024;
    #pragma unroll
    for (int ntd = 0; ntd < 8; ntd++) {
        float2 v0 = { o[ntd][0] * inv0, o[ntd][1] * inv0 };
        float2 v1 = { o[ntd][2] * inv1, o[ntd][3] * inv1 };
        *(float2*)(out0 + ntd * 8 + 2 * lr) = v0;
        *(float2*)(out1 + ntd * 8 + 2 * lr) = v1;
    }
}

// ---------------------------------------------------------------------------
// Kernel 3: output projection.  BM=128, BN=128, BK=16, 512 thr / 16 warps,
// warp tile 32m x 32n.  Fragment-ordered double-buffered smem (32 KB).
// ---------------------------------------------------------------------------
__global__ __launch_bounds__(512)
void outproj_mma(const float* __restrict__ Wo, const float* __restrict__ bo,
                 float* __restrict__ out)
{
    __shared__ uint32_t Af[2][QKV_ASZ];
    __shared__ uint32_t Bf[2][OP_BSZ];

    const int tid  = threadIdx.x;
    const int warp = tid >> 5;
    const int lane = tid & 31;
    const int wm   = warp >> 2;
    const int wn   = warp & 3;
    const int m0   = blockIdx.x * 128;
    const int n0   = blockIdx.y * 128;

    const int row = tid >> 2;
    const int c4  = (tid & 3) * 4;
    const float* a_src = g_ctx + (size_t)(m0 + row) * 1024 + c4;
    const float* b_src = Wo    + (size_t)(n0 + row) * 1024 + c4;

    const int sK   = c4 >> 3;
    const int regA = ((row & 15) >> 3) + (((c4 & 7) >> 2) << 1);
    const int a_off = (sK * 8 + (row >> 4)) * 128 + (row & 7) * 16 + regA;
    const int regB = (c4 & 7) >> 2;
    const int n8   = row >> 3;
    const int b_off = (sK * 8 + (n8 >> 1)) * 128 + (row & 7) * 16 + (n8 & 1) * 2 + regB;

    float acc[2][4][4];
    #pragma unroll
    for (int mt = 0; mt < 2; mt++)
        #pragma unroll
        for (int nt = 0; nt < 4; nt++)
            #pragma unroll
            for (int e = 0; e < 4; e++) acc[mt][nt][e] = 0.f;

    float4 ra = *(const float4*)(a_src);
    float4 rb = *(const float4*)(b_src);

    for (int it = 0; it < 64; ++it) {
        const int st = it & 1;
        Af[st][a_off     ] = f2tf32(ra.x);
        Af[st][a_off +  4] = f2tf32(ra.y);
        Af[st][a_off +  8] = f2tf32(ra.z);
        Af[st][a_off + 12] = f2tf32(ra.w);
        Bf[st][b_off     ] = f2tf32(rb.x);
        Bf[st][b_off +  4] = f2tf32(rb.y);
        Bf[st][b_off +  8] = f2tf32(rb.z);
        Bf[st][b_off + 12] = f2tf32(rb.w);
        __syncthreads();

        if (it < 63) {
            int k0 = (it + 1) * 16;
            ra = *(const float4*)(a_src + k0);
            rb = *(const float4*)(b_src + k0);
        }

        const uint32_t* Ac = Af[st];
        const uint32_t* Bc = Bf[st];
        #pragma unroll
        for (int s = 0; s < 2; s++) {
            uint4 av0 = *(const uint4*)&Ac[(s * 8 + wm * 2 + 0) * 128 + lane * 4];
            uint4 av1 = *(const uint4*)&Ac[(s * 8 + wm * 2 + 1) * 128 + lane * 4];
            uint32_t af0[4] = {av0.x, av0.y, av0.z, av0.w};
            uint32_t af1[4] = {av1.x, av1.y, av1.z, av1.w};
            #pragma unroll
            for (int p = 0; p < 2; p++) {
                uint4 bv = *(const uint4*)&Bc[(s * 8 + wn * 2 + p) * 128 + lane * 4];
                uint32_t bfe[2] = {bv.x, bv.y};
                uint32_t bfo[2] = {bv.z, bv.w};
                mma_tf32(acc[0][2*p  ], af0, bfe);
                mma_tf32(acc[1][2*p  ], af1, bfe);
                mma_tf32(acc[0][2*p+1], af0, bfo);
                mma_tf32(acc[1][2*p+1], af1, bfo);
            }
        }
        __syncthreads();
    }

    const int lq = lane >> 2;
    const int lr = lane & 3;
    #pragma unroll
    for (int mt = 0; mt < 2; mt++) {
        #pragma unroll
        for (int half = 0; half < 2; half++) {
            int m = m0 + wm * 32 + mt * 16 + half * 8 + lq;
            float* rowp = out + (size_t)m * 1024 + n0;
            #pragma unroll
            for (int nt = 0; nt < 4; nt++) {
                int n = wn * 32 + nt * 8 + 2 * lr;
                float2 v;
                v.x = acc[mt][nt][half * 2 + 0] + bo[n0 + n];
                v.y = acc[mt][nt][half * 2 + 1] + bo[n0 + n + 1];
                *(float2*)(rowp + n) = v;
            }
        }
    }
}

// ---------------------------------------------------------------------------
extern "C" void kernel_launch(void* const* d_in, const int* in_sizes, int n_in,
                              void* d_out, int out_size)
{
    const float* x  = (const float*)d_in[0];
    const float* Wq = (const float*)d_in[1];
    const float* bq = (const float*)d_in[2];
    const float* Wk = (const float*)d_in[3];
    const float* bk = (const float*)d_in[4];
    const float* Wv = (const float*)d_in[5];
    const float* bv = (const float*)d_in[6];
    const float* Wo = (const float*)d_in[7];
    const float* bo = (const float*)d_in[8];
    float* out = (float*)d_out;

    qkv_mma<<<MQKV / 128, 512>>>(x, Wq, bq, Wk, bk, Wv, bv);

    dim3 g2(BB_ * HH_, SP_ / 128);
    attn_mma<<<g2, 256>>>();

    dim3 g3(MOUT / 128, EE_ / 128);
    outproj_mma<<<g3, 512>>>(Wo, bo, out);
}

// round 8
// speedup vs baseline: 1.4449x; 1.4449x over previous
#include <cuda_runtime.h>
#include <stdint.h>

// Problem constants
#define BB_  4
#define SS_  8192
#define EE_  1024
#define HH_  16
#define DD_  64
#define SP_  512
#define MQKV (BB_*SS_)
#define MOUT (BB_*SP_)

// Scratch: q/k/v/ctx hold tf32 bit patterns; weight copies pre-converted to tf32
__device__ uint32_t g_q[BB_*HH_*SP_*DD_];     // [B,H,S',D] tf32 bits
__device__ uint32_t g_k[BB_*HH_*SP_*DD_];
__device__ uint32_t g_v[BB_*HH_*SP_*DD_];
__device__ uint32_t g_ctx[BB_*SP_*EE_];       // [B,S',E]  tf32 bits
__device__ uint32_t g_wq[DD_*EE_];
__device__ uint32_t g_wk[DD_*EE_];
__device__ uint32_t g_wv[DD_*EE_];
__device__ uint32_t g_wo[EE_*EE_];

// ---------------------------------------------------------------------------
// helpers
// ---------------------------------------------------------------------------
__device__ __forceinline__ uint32_t f2tf32(float f) {
    uint32_t u;
    asm("cvt.rna.tf32.f32 %0, %1;" : "=r"(u) : "f"(f));
    return u;
}

__device__ __forceinline__ void mma_tf32(float c[4], const uint32_t a[4], const uint32_t b[2]) {
    asm volatile(
        "mma.sync.aligned.m16n8k8.row.col.f32.tf32.tf32.f32 "
        "{%0,%1,%2,%3}, {%4,%5,%6,%7}, {%8,%9}, {%0,%1,%2,%3};\n"
        : "+f"(c[0]), "+f"(c[1]), "+f"(c[2]), "+f"(c[3])
        : "r"(a[0]), "r"(a[1]), "r"(a[2]), "r"(a[3]), "r"(b[0]), "r"(b[1]));
}

__device__ __forceinline__ uint32_t smem_u32(const void* p) {
    return (uint32_t)__cvta_generic_to_shared(p);
}
#define CP16(dst, src) asm volatile("cp.async.cg.shared.global [%0], [%1], 16;\n" :: "r"(dst), "l"(src))
#define CP_COMMIT()    asm volatile("cp.async.commit_group;\n" ::: "memory")
#define CP_WAIT1()     asm volatile("cp.async.wait_group 1;\n" ::: "memory")

#define S20 20   // smem row stride (16 data + 4 pad; 80B rows keep cp.async 16B-aligned)

// ---------------------------------------------------------------------------
// Kernel 0: pre-convert weights to tf32 bits (runs once per launch, ~3us)
// ---------------------------------------------------------------------------
__global__ __launch_bounds__(256)
void cvt_weights(const float* __restrict__ Wq, const float* __restrict__ Wk,
                 const float* __restrict__ Wv, const float* __restrict__ Wo)
{
    const int i = blockIdx.x * 256 + threadIdx.x;   // 0..65535
    g_wq[i] = f2tf32(Wq[i]);
    g_wk[i] = f2tf32(Wk[i]);
    g_wv[i] = f2tf32(Wv[i]);
    #pragma unroll
    for (int j = 0; j < 16; j++)
        g_wo[i + j * 65536] = f2tf32(Wo[i + j * 65536]);
}

// ---------------------------------------------------------------------------
// Kernel 1: fused QKV projection, TF32 mma, 3-stage cp.async, BK=16.
// 512 threads / 16 warps, warp tile 32m x 48n.  BM=128, BN=192.
// A fragments: CVT in loop (x is fp32).  B fragments: raw tf32 bits.
// Epilogue stores Q/K/V as tf32 bits.
// ---------------------------------------------------------------------------
#define QKV_ASZ (128 * S20)
#define QKV_BSZ (192 * S20)
#define QKV_SMEM ((3 * QKV_ASZ + 3 * QKV_BSZ) * 4)

__global__ __launch_bounds__(512)
void qkv_mma(const float* __restrict__ x,
             const float* __restrict__ bq, const float* __restrict__ bk,
             const float* __restrict__ bv)
{
    extern __shared__ uint32_t sm[];
    uint32_t* As = sm;                     // 3 stages of [128][S20] (fp32 bits)
    uint32_t* Bs = sm + 3 * QKV_ASZ;       // 3 stages of [192][S20] (tf32 bits)

    const int tid  = threadIdx.x;
    const int warp = tid >> 5;
    const int lane = tid & 31;
    const int wm   = warp >> 2;
    const int wn   = warp & 3;
    const int m0   = blockIdx.x * 128;
    const int lq   = lane >> 2;
    const int lr   = lane & 3;

    // A tile: 128x16 = 512 float4, 1 per thread
    const int arow = tid >> 2;
    const int ac4  = (tid & 3) * 4;
    const float* a_src = x + (size_t)(m0 + arow) * 1024 + ac4;
    uint32_t a_dst[3];
    #pragma unroll
    for (int s = 0; s < 3; s++)
        a_dst[s] = smem_u32(&As[s * QKV_ASZ + arow * S20 + ac4]);

    // B tile: 192x16 = 768 float4
    const int b1row = tid >> 2;                       // 0..127 : Wq|Wk
    const uint32_t* b1_src = (b1row < 64 ? g_wq + (size_t)b1row * 1024
                                         : g_wk + (size_t)(b1row - 64) * 1024) + ac4;
    uint32_t b1_dst[3];
    #pragma unroll
    for (int s = 0; s < 3; s++)
        b1_dst[s] = smem_u32(&Bs[s * QKV_BSZ + b1row * S20 + ac4]);

    const bool has2 = (tid < 256);
    const int b2row = 128 + (tid >> 2);               // 128..191 : Wv
    const uint32_t* b2_src = g_wv + (size_t)(tid >> 2) * 1024 + ac4;
    uint32_t b2_dst[3];
    #pragma unroll
    for (int s = 0; s < 3; s++)
        b2_dst[s] = smem_u32(&Bs[s * QKV_BSZ + b2row * S20 + ac4]);

    float acc[2][6][4];
    #pragma unroll
    for (int mt = 0; mt < 2; mt++)
        #pragma unroll
        for (int nt = 0; nt < 6; nt++)
            #pragma unroll
            for (int e = 0; e < 4; e++) acc[mt][nt][e] = 0.f;

    #pragma unroll
    for (int s = 0; s < 2; s++) {
        int k0 = s * 16;
        CP16(a_dst[s], a_src + k0);
        CP16(b1_dst[s], b1_src + k0);
        if (has2) CP16(b2_dst[s], b2_src + k0);
        CP_COMMIT();
    }

    for (int it = 0; it < 64; ++it) {
        CP_WAIT1();
        __syncthreads();

        if (it + 2 < 64) {
            int k0 = (it + 2) * 16;
            int s  = (it + 2) % 3;
            CP16(a_dst[s], a_src + k0);
            CP16(b1_dst[s], b1_src + k0);
            if (has2) CP16(b2_dst[s], b2_src + k0);
        }
        CP_COMMIT();

        const uint32_t* Ac = As + (it % 3) * QKV_ASZ;
        const uint32_t* Bc = Bs + (it % 3) * QKV_BSZ;

        #pragma unroll
        for (int ks = 0; ks < 16; ks += 8) {
            uint32_t af[2][4];
            #pragma unroll
            for (int mt = 0; mt < 2; mt++) {
                int mb = wm * 32 + mt * 16;
                af[mt][0] = f2tf32(__uint_as_float(Ac[(mb +     lq) * S20 + ks + lr]));
                af[mt][1] = f2tf32(__uint_as_float(Ac[(mb + 8 + lq) * S20 + ks + lr]));
                af[mt][2] = f2tf32(__uint_as_float(Ac[(mb +     lq) * S20 + ks + lr + 4]));
                af[mt][3] = f2tf32(__uint_as_float(Ac[(mb + 8 + lq) * S20 + ks + lr + 4]));
            }
            #pragma unroll
            for (int nt = 0; nt < 6; nt++) {
                int nb = wn * 48 + nt * 8;
                uint32_t bf[2];
                bf[0] = Bc[(nb + lq) * S20 + ks + lr];
                bf[1] = Bc[(nb + lq) * S20 + ks + lr + 4];
                mma_tf32(acc[0][nt], af[0], bf);
                mma_tf32(acc[1][nt], af[1], bf);
            }
        }
    }

    // Epilogue: bias + scatter into [B,H,S',D] as tf32 bits
    #pragma unroll
    for (int mt = 0; mt < 2; mt++) {
        #pragma unroll
        for (int half = 0; half < 2; half++) {
            int m  = m0 + wm * 32 + mt * 16 + half * 8 + lq;
            int bb = m >> 13;
            int s  = m & 8191;
            int sp = s >> 4;
            int h  = s & 15;
            size_t rowoff = ((size_t)(bb * 16 + h) * 512 + sp) * 64;
            #pragma unroll
            for (int nt = 0; nt < 6; nt++) {
                int n   = wn * 48 + nt * 8 + 2 * lr;
                int mat = n >> 6;
                int nn  = n & 63;
                uint32_t* dst = (mat == 0) ? g_q : (mat == 1 ? g_k : g_v);
                const float* bias = (mat == 0) ? bq : (mat == 1 ? bk : bv);
                uint2 v;
                v.x = f2tf32(acc[mt][nt][half * 2 + 0] + bias[nn]);
                v.y = f2tf32(acc[mt][nt][half * 2 + 1] + bias[nn + 1]);
                *(uint2*)(dst + rowoff + nn) = v;
            }
        }
    }
}

// ---------------------------------------------------------------------------
// Kernel 2: attention.  Q/K/V arrive as tf32 bits -> no CVT on K/V fragments.
// Q scale 0.125 is a power of two: exact on tf32 values, no re-convert.
// ctx written as tf32 bits.
// ---------------------------------------------------------------------------
#define KSTR 68
#define VSTR 72

__global__ __launch_bounds__(256)
void attn_mma()
{
    __shared__ uint32_t Ks[64 * KSTR];
    __shared__ uint32_t Vs[64 * VSTR];

    const int bh   = blockIdx.x;
    const int qt   = blockIdx.y;
    const int tid  = threadIdx.x;
    const int warp = tid >> 5;
    const int lane = tid & 31;
    const int lq   = lane >> 2;
    const int lr   = lane & 3;

    const uint32_t* qbase = g_q + ((size_t)bh * 512 + qt * 128 + warp * 16) * 64;
    uint32_t qa[8][4];
    #pragma unroll
    for (int ks = 0; ks < 8; ks++) {
        qa[ks][0] = __float_as_uint(__uint_as_float(qbase[(size_t)lq       * 64 + ks * 8 + lr    ]) * 0.125f);
        qa[ks][1] = __float_as_uint(__uint_as_float(qbase[(size_t)(lq + 8) * 64 + ks * 8 + lr    ]) * 0.125f);
        qa[ks][2] = __float_as_uint(__uint_as_float(qbase[(size_t)lq       * 64 + ks * 8 + lr + 4]) * 0.125f);
        qa[ks][3] = __float_as_uint(__uint_as_float(qbase[(size_t)(lq + 8) * 64 + ks * 8 + lr + 4]) * 0.125f);
    }

    float o[8][4];
    #pragma unroll
    for (int nt = 0; nt < 8; nt++)
        #pragma unroll
        for (int e = 0; e < 4; e++) o[nt][e] = 0.f;
    float lsum0 = 0.f, lsum1 = 0.f;

    const uint32_t* kb = g_k + (size_t)bh * 512 * 64;
    const uint32_t* vb = g_v + (size_t)bh * 512 * 64;

    for (int kt = 0; kt < 8; kt++) {
        __syncthreads();
        #pragma unroll
        for (int i = 0; i < 4; i++) {
            int idx = tid + i * 256;
            int row = idx >> 4, c4 = (idx & 15) << 2;
            *(uint4*)(Ks + row * KSTR + c4) = *(const uint4*)(kb + (size_t)kt * 4096 + idx * 4);
            *(uint4*)(Vs + row * VSTR + c4) = *(const uint4*)(vb + (size_t)kt * 4096 + idx * 4);
        }
        __syncthreads();

        float sc[8][4];
        #pragma unroll
        for (int nt = 0; nt < 8; nt++) {
            sc[nt][0] = sc[nt][1] = sc[nt][2] = sc[nt][3] = 0.f;
            #pragma unroll
            for (int ks = 0; ks < 8; ks++) {
                uint32_t bf[2];
                bf[0] = Ks[(nt * 8 + lq) * KSTR + ks * 8 + lr    ];
                bf[1] = Ks[(nt * 8 + lq) * KSTR + ks * 8 + lr + 4];
                mma_tf32(sc[nt], qa[ks], bf);
            }
        }

        #pragma unroll
        for (int nt = 0; nt < 8; nt++) {
            float p0 = __expf(sc[nt][0]), p1 = __expf(sc[nt][1]);
            float p2 = __expf(sc[nt][2]), p3 = __expf(sc[nt][3]);
            sc[nt][0] = p0; sc[nt][1] = p1; sc[nt][2] = p2; sc[nt][3] = p3;
            lsum0 += p0 + p1;
            lsum1 += p2 + p3;
        }

        #pragma unroll
        for (int ks = 0; ks < 8; ks++) {
            int src  = (lane & ~3) | (lr >> 1);
            float t0 = __shfl_sync(0xffffffffu, sc[ks][0], src);
            float t1 = __shfl_sync(0xffffffffu, sc[ks][1], src);
            float t2 = __shfl_sync(0xffffffffu, sc[ks][2], src);
            float t3 = __shfl_sync(0xffffffffu, sc[ks][3], src);
            float u0 = __shfl_sync(0xffffffffu, sc[ks][0], src + 2);
            float u1 = __shfl_sync(0xffffffffu, sc[ks][1], src + 2);
            float u2 = __shfl_sync(0xffffffffu, sc[ks][2], src + 2);
            float u3 = __shfl_sync(0xffffffffu, sc[ks][3], src + 2);
            uint32_t pa[4];
            pa[0] = f2tf32((lr & 1) ? t1 : t0);
            pa[1] = f2tf32((lr & 1) ? t3 : t2);
            pa[2] = f2tf32((lr & 1) ? u1 : u0);
            pa[3] = f2tf32((lr & 1) ? u3 : u2);
            #pragma unroll
            for (int ntd = 0; ntd < 8; ntd++) {
                uint32_t bf[2];
                bf[0] = Vs[(ks * 8 + lr    ) * VSTR + ntd * 8 + lq];
                bf[1] = Vs[(ks * 8 + lr + 4) * VSTR + ntd * 8 + lq];
                mma_tf32(o[ntd], pa, bf);
            }
        }
    }

    lsum0 += __shfl_xor_sync(0xffffffffu, lsum0, 1);
    lsum0 += __shfl_xor_sync(0xffffffffu, lsum0, 2);
    lsum1 += __shfl_xor_sync(0xffffffffu, lsum1, 1);
    lsum1 += __shfl_xor_sync(0xffffffffu, lsum1, 2);
    const float inv0 = 1.f / lsum0;
    const float inv1 = 1.f / lsum1;

    const int bb = bh >> 4, h = bh & 15;
    const int qrow0 = qt * 128 + warp * 16 + lq;
    uint32_t* out0 = g_ctx + ((size_t)(bb * 512 + qrow0)) * 1024 + h * 64;
    uint32_t* out1 = out0 + (size_t)8 * 1024;
    #pragma unroll
    for (int ntd = 0; ntd < 8; ntd++) {
        uint2 v0 = { f2tf32(o[ntd][0] * inv0), f2tf32(o[ntd][1] * inv0) };
        uint2 v1 = { f2tf32(o[ntd][2] * inv1), f2tf32(o[ntd][3] * inv1) };
        *(uint2*)(out0 + ntd * 8 + 2 * lr) = v0;
        *(uint2*)(out1 + ntd * 8 + 2 * lr) = v1;
    }
}

// ---------------------------------------------------------------------------
// Kernel 3: output projection.  A (ctx) and B (Wo) already tf32 bits ->
// zero CVTs in the inner loop.  3-stage cp.async, BK=16, 512 threads.
// ---------------------------------------------------------------------------
#define OP_TSZ (128 * S20)
#define OP_SMEM ((6 * OP_TSZ) * 4)

__global__ __launch_bounds__(512)
void outproj_mma(const float* __restrict__ bo, float* __restrict__ out)
{
    extern __shared__ uint32_t sm[];
    uint32_t* As = sm;
    uint32_t* Bs = sm + 3 * OP_TSZ;

    const int tid  = threadIdx.x;
    const int warp = tid >> 5;
    const int lane = tid & 31;
    const int wm   = warp >> 2;
    const int wn   = warp & 3;
    const int m0   = blockIdx.x * 128;
    const int n0   = blockIdx.y * 128;
    const int lq   = lane >> 2;
    const int lr   = lane & 3;

    const int row = tid >> 2;
    const int c4  = (tid & 3) * 4;
    const uint32_t* a_src = g_ctx + (size_t)(m0 + row) * 1024 + c4;
    const uint32_t* b_src = g_wo  + (size_t)(n0 + row) * 1024 + c4;
    uint32_t a_dst[3], b_dst[3];
    #pragma unroll
    for (int s = 0; s < 3; s++) {
        a_dst[s] = smem_u32(&As[s * OP_TSZ + row * S20 + c4]);
        b_dst[s] = smem_u32(&Bs[s * OP_TSZ + row * S20 + c4]);
    }

    float acc[2][4][4];
    #pragma unroll
    for (int mt = 0; mt < 2; mt++)
        #pragma unroll
        for (int nt = 0; nt < 4; nt++)
            #pragma unroll
            for (int e = 0; e < 4; e++) acc[mt][nt][e] = 0.f;

    #pragma unroll
    for (int s = 0; s < 2; s++) {
        int k0 = s * 16;
        CP16(a_dst[s], a_src + k0);
        CP16(b_dst[s], b_src + k0);
        CP_COMMIT();
    }

    for (int it = 0; it < 64; ++it) {
        CP_WAIT1();
        __syncthreads();

        if (it + 2 < 64) {
            int k0 = (it + 2) * 16;
            int s  = (it + 2) % 3;
            CP16(a_dst[s], a_src + k0);
            CP16(b_dst[s], b_src + k0);
        }
        CP_COMMIT();

        const uint32_t* Ac = As + (it % 3) * OP_TSZ;
        const uint32_t* Bc = Bs + (it % 3) * OP_TSZ;

        #pragma unroll
        for (int ks = 0; ks < 16; ks += 8) {
            uint32_t af[2][4];
            #pragma unroll
            for (int mt = 0; mt < 2; mt++) {
                int mb = wm * 32 + mt * 16;
                af[mt][0] = Ac[(mb +     lq) * S20 + ks + lr];
                af[mt][1] = Ac[(mb + 8 + lq) * S20 + ks + lr];
                af[mt][2] = Ac[(mb +     lq) * S20 + ks + lr + 4];
                af[mt][3] = Ac[(mb + 8 + lq) * S20 + ks + lr + 4];
            }
            #pragma unroll
            for (int nt = 0; nt < 4; nt++) {
                int nb = wn * 32 + nt * 8;
                uint32_t bf[2];
                bf[0] = Bc[(nb + lq) * S20 + ks + lr];
                bf[1] = Bc[(nb + lq) * S20 + ks + lr + 4];
                mma_tf32(acc[0][nt], af[0], bf);
                mma_tf32(acc[1][nt], af[1], bf);
            }
        }
    }

    #pragma unroll
    for (int mt = 0; mt < 2; mt++) {
        #pragma unroll
        for (int half = 0; half < 2; half++) {
            int m = m0 + wm * 32 + mt * 16 + half * 8 + lq;
            float* rowp = out + (size_t)m * 1024 + n0;
            #pragma unroll
            for (int nt = 0; nt < 4; nt++) {
                int n = wn * 32 + nt * 8 + 2 * lr;
                float2 v;
                v.x = acc[mt][nt][half * 2 + 0] + bo[n0 + n];
                v.y = acc[mt][nt][half * 2 + 1] + bo[n0 + n + 1];
                *(float2*)(rowp + n) = v;
            }
        }
    }
}

// ---------------------------------------------------------------------------
extern "C" void kernel_launch(void* const* d_in, const int* in_sizes, int n_in,
                              void* d_out, int out_size)
{
    const float* x  = (const float*)d_in[0];
    const float* Wq = (const float*)d_in[1];
    const float* bq = (const float*)d_in[2];
    const float* Wk = (const float*)d_in[3];
    const float* bk = (const float*)d_in[4];
    const float* Wv = (const float*)d_in[5];
    const float* bv = (const float*)d_in[6];
    const float* Wo = (const float*)d_in[7];
    const float* bo = (const float*)d_in[8];
    float* out = (float*)d_out;

    static bool attr_done = false;
    if (!attr_done) {
        cudaFuncSetAttribute(qkv_mma, cudaFuncAttributeMaxDynamicSharedMemorySize, QKV_SMEM);
        cudaFuncSetAttribute(outproj_mma, cudaFuncAttributeMaxDynamicSharedMemorySize, OP_SMEM);
        attr_done = true;
    }

    cvt_weights<<<256, 256>>>(Wq, Wk, Wv, Wo);

    qkv_mma<<<MQKV / 128, 512, QKV_SMEM>>>(x, bq, bk, bv);

    dim3 g2(BB_ * HH_, SP_ / 128);
    attn_mma<<<g2, 256>>>();

    dim3 g3(MOUT / 128, EE_ / 128);
    outproj_mma<<<g3, 512, OP_SMEM>>>(bo, out);
}

// round 9
// speedup vs baseline: 1.5662x; 1.0840x over previous
#include <cuda_runtime.h>
#include <stdint.h>

// Problem constants
#define BB_  4
#define SS_  8192
#define EE_  1024
#define HH_  16
#define DD_  64
#define SP_  512
#define MQKV (BB_*SS_)
#define MOUT (BB_*SP_)

// Scratch: q/k/v/ctx hold tf32 bit patterns; weights pre-converted AND
// pre-swizzled into mma-fragment order.
__device__ uint32_t g_q[BB_*HH_*SP_*DD_];     // [B,H,S',D] tf32 bits
__device__ uint32_t g_k[BB_*HH_*SP_*DD_];
__device__ uint32_t g_v[BB_*HH_*SP_*DD_];
__device__ uint32_t g_ctx[BB_*SP_*EE_];       // [B,S',E]  tf32 bits
__device__ uint32_t g_wqkv[192*EE_];          // fragment-ordered [Wq;Wk;Wv]
__device__ uint32_t g_wo[EE_*EE_];            // fragment-ordered Wo

// ---------------------------------------------------------------------------
// helpers
// ---------------------------------------------------------------------------
__device__ __forceinline__ uint32_t f2tf32(float f) {
    uint32_t u;
    asm("cvt.rna.tf32.f32 %0, %1;" : "=r"(u) : "f"(f));
    return u;
}

__device__ __forceinline__ void mma_tf32(float c[4], const uint32_t a[4], const uint32_t b[2]) {
    asm volatile(
        "mma.sync.aligned.m16n8k8.row.col.f32.tf32.tf32.f32 "
        "{%0,%1,%2,%3}, {%4,%5,%6,%7}, {%8,%9}, {%0,%1,%2,%3};\n"
        : "+f"(c[0]), "+f"(c[1]), "+f"(c[2]), "+f"(c[3])
        : "r"(a[0]), "r"(a[1]), "r"(a[2]), "r"(a[3]), "r"(b[0]), "r"(b[1]));
}

__device__ __forceinline__ uint32_t smem_u32(const void* p) {
    return (uint32_t)__cvta_generic_to_shared(p);
}
#define CP16(dst, src) asm volatile("cp.async.cg.shared.global [%0], [%1], 16;\n" :: "r"(dst), "l"(src))
#define CP_COMMIT()    asm volatile("cp.async.commit_group;\n" ::: "memory")
#define CP_WAIT1()     asm volatile("cp.async.wait_group 1;\n" ::: "memory")

#define S20 20   // smem row stride for the A (activation) tiles

// Fragment-pair tile: 16 n-rows x 8 k, 128 u32.
// idx(n16, k8) = ((n16%8)*4 + (k8%4))*4 + (n16/8)*2 + (k8/4)
// A warp's uint4 at [lane*4] = {bf_even[0], bf_even[1], bf_odd[0], bf_odd[1]}.
__device__ __forceinline__ int frag_idx(int n16, int k8) {
    return ((n16 & 7) * 4 + (k8 & 3)) * 4 + ((n16 >> 3) << 1) + (k8 >> 2);
}

// ---------------------------------------------------------------------------
// Kernel 0: pre-convert + pre-swizzle weights (once per launch, ~5us)
//
// g_wqkv: rows n 0..63 = Wq, 64..127 = Wk, 128..191 = Wv.
//   addr = ((it*2+ks)*12 + n/16)*128 + frag_idx(n%16, k%8)
//   -> for a fixed k16-iteration `it`, the full 192xk16 tile is 3072
//      contiguous u32 (12 KB) at g_wqkv + it*3072.
// g_wo: addr = (((nb*64+it)*2+ks)*8 + nn/16)*128 + frag_idx(nn%16, k%8)
//   (nb = n/128, nn = n%128) -> per (nb, it): 2048 contiguous u32 (8 KB).
// ---------------------------------------------------------------------------
__global__ __launch_bounds__(256)
void cvt_weights(const float* __restrict__ Wq, const float* __restrict__ Wk,
                 const float* __restrict__ Wv, const float* __restrict__ Wo)
{
    const int idx = blockIdx.x * 256 + threadIdx.x;   // 0..65535
    const int row = idx >> 10;
    const int k   = idx & 1023;
    const int it  = k >> 4;
    const int ks  = (k >> 3) & 1;
    const int k8  = k & 7;

    // qkv weights
    {
        const float* Ws[3] = { Wq, Wk, Wv };
        #pragma unroll
        for (int mat = 0; mat < 3; mat++) {
            int n = mat * 64 + row;
            int addr = ((it * 2 + ks) * 12 + (n >> 4)) * 128 + frag_idx(n & 15, k8);
            g_wqkv[addr] = f2tf32(Ws[mat][row * 1024 + k]);
        }
    }
    // Wo
    #pragma unroll
    for (int j = 0; j < 16; j++) {
        int e  = idx + j * 65536;
        int n  = e >> 10;
        int kk = e & 1023;
        int it2 = kk >> 4, ks2 = (kk >> 3) & 1, k82 = kk & 7;
        int nb = n >> 7, nn = n & 127;
        int addr = (((nb * 64 + it2) * 2 + ks2) * 8 + (nn >> 4)) * 128 + frag_idx(nn & 15, k82);
        g_wo[addr] = f2tf32(Wo[(size_t)n * 1024 + kk]);
    }
}

// ---------------------------------------------------------------------------
// Kernel 1: fused QKV projection, TF32 mma, 3-stage cp.async, BK=16.
// 512 threads / 16 warps, warp tile 32m x 48n.  BM=128, BN=192.
// A: S20-padded fp32 + in-loop CVT.  B: fragment-ordered tf32 -> LDS.128.
// ---------------------------------------------------------------------------
#define QKV_ASTG (128 * S20)   // 2560 u32
#define QKV_BSTG 3072          // u32 (12 pair-tiles x 2 ks x 128)
#define QKV_SMEM ((3 * QKV_ASTG + 3 * QKV_BSTG) * 4)

__global__ __launch_bounds__(512)
void qkv_mma(const float* __restrict__ x,
             const float* __restrict__ bq, const float* __restrict__ bk,
             const float* __restrict__ bv)
{
    extern __shared__ uint32_t sm[];
    uint32_t* As = sm;                      // 3 stages of [128][S20]
    uint32_t* Bs = sm + 3 * QKV_ASTG;       // 3 stages of 3072 (fragment order)

    const int tid  = threadIdx.x;
    const int warp = tid >> 5;
    const int lane = tid & 31;
    const int wm   = warp >> 2;
    const int wn   = warp & 3;
    const int m0   = blockIdx.x * 128;
    const int lq   = lane >> 2;
    const int lr   = lane & 3;

    // A tile: 128x16 = 512 float4, 1 per thread
    const int arow = tid >> 2;
    const int ac4  = (tid & 3) * 4;
    const float* a_src = x + (size_t)(m0 + arow) * 1024 + ac4;
    uint32_t a_dst[3];
    #pragma unroll
    for (int s = 0; s < 3; s++)
        a_dst[s] = smem_u32(&As[s * QKV_ASTG + arow * S20 + ac4]);

    // B tile: 3072 u32 = 768 16B-chunks; all threads chunk tid, tid<256 also 512+tid
    const bool has2 = (tid < 256);
    uint32_t b_dst1[3], b_dst2[3];
    #pragma unroll
    for (int s = 0; s < 3; s++) {
        b_dst1[s] = smem_u32(&Bs[s * QKV_BSTG + tid * 4]);
        b_dst2[s] = smem_u32(&Bs[s * QKV_BSTG + (512 + tid) * 4]);
    }

    float acc[2][6][4];
    #pragma unroll
    for (int mt = 0; mt < 2; mt++)
        #pragma unroll
        for (int nt = 0; nt < 6; nt++)
            #pragma unroll
            for (int e = 0; e < 4; e++) acc[mt][nt][e] = 0.f;

    #pragma unroll
    for (int s = 0; s < 2; s++) {
        CP16(a_dst[s], a_src + s * 16);
        CP16(b_dst1[s], g_wqkv + s * QKV_BSTG + tid * 4);
        if (has2) CP16(b_dst2[s], g_wqkv + s * QKV_BSTG + (512 + tid) * 4);
        CP_COMMIT();
    }

    for (int it = 0; it < 64; ++it) {
        CP_WAIT1();
        __syncthreads();

        if (it + 2 < 64) {
            int s = (it + 2) % 3;
            CP16(a_dst[s], a_src + (it + 2) * 16);
            CP16(b_dst1[s], g_wqkv + (it + 2) * QKV_BSTG + tid * 4);
            if (has2) CP16(b_dst2[s], g_wqkv + (it + 2) * QKV_BSTG + (512 + tid) * 4);
        }
        CP_COMMIT();

        const uint32_t* Ac = As + (it % 3) * QKV_ASTG;
        const uint32_t* Bc = Bs + (it % 3) * QKV_BSTG;

        #pragma unroll
        for (int ks = 0; ks < 2; ks++) {
            uint32_t af[2][4];
            #pragma unroll
            for (int mt = 0; mt < 2; mt++) {
                int mb = wm * 32 + mt * 16;
                af[mt][0] = f2tf32(__uint_as_float(Ac[(mb +     lq) * S20 + ks * 8 + lr]));
                af[mt][1] = f2tf32(__uint_as_float(Ac[(mb + 8 + lq) * S20 + ks * 8 + lr]));
                af[mt][2] = f2tf32(__uint_as_float(Ac[(mb +     lq) * S20 + ks * 8 + lr + 4]));
                af[mt][3] = f2tf32(__uint_as_float(Ac[(mb + 8 + lq) * S20 + ks * 8 + lr + 4]));
            }
            #pragma unroll
            for (int pl = 0; pl < 3; pl++) {
                uint4 bv = *(const uint4*)&Bc[(ks * 12 + wn * 3 + pl) * 128 + lane * 4];
                uint32_t bfe[2] = { bv.x, bv.y };
                uint32_t bfo[2] = { bv.z, bv.w };
                mma_tf32(acc[0][2*pl  ], af[0], bfe);
                mma_tf32(acc[1][2*pl  ], af[1], bfe);
                mma_tf32(acc[0][2*pl+1], af[0], bfo);
                mma_tf32(acc[1][2*pl+1], af[1], bfo);
            }
        }
    }

    // Epilogue: bias + scatter into [B,H,S',D] as tf32 bits
    #pragma unroll
    for (int mt = 0; mt < 2; mt++) {
        #pragma unroll
        for (int half = 0; half < 2; half++) {
            int m  = m0 + wm * 32 + mt * 16 + half * 8 + lq;
            int bb = m >> 13;
            int s  = m & 8191;
            int sp = s >> 4;
            int h  = s & 15;
            size_t rowoff = ((size_t)(bb * 16 + h) * 512 + sp) * 64;
            #pragma unroll
            for (int nt = 0; nt < 6; nt++) {
                int n   = wn * 48 + nt * 8 + 2 * lr;
                int mat = n >> 6;
                int nn  = n & 63;
                uint32_t* dst = (mat == 0) ? g_q : (mat == 1 ? g_k : g_v);
                const float* bias = (mat == 0) ? bq : (mat == 1 ? bk : bv);
                uint2 v;
                v.x = f2tf32(acc[mt][nt][half * 2 + 0] + bias[nn]);
                v.y = f2tf32(acc[mt][nt][half * 2 + 1] + bias[nn + 1]);
                *(uint2*)(dst + rowoff + nn) = v;
            }
        }
    }
}

// ---------------------------------------------------------------------------
// Kernel 2: attention (unchanged from R7 — tf32 bits in, tf32 bits out).
// ---------------------------------------------------------------------------
#define KSTR 68
#define VSTR 72

__global__ __launch_bounds__(256)
void attn_mma()
{
    __shared__ uint32_t Ks[64 * KSTR];
    __shared__ uint32_t Vs[64 * VSTR];

    const int bh   = blockIdx.x;
    const int qt   = blockIdx.y;
    const int tid  = threadIdx.x;
    const int warp = tid >> 5;
    const int lane = tid & 31;
    const int lq   = lane >> 2;
    const int lr   = lane & 3;

    const uint32_t* qbase = g_q + ((size_t)bh * 512 + qt * 128 + warp * 16) * 64;
    uint32_t qa[8][4];
    #pragma unroll
    for (int ks = 0; ks < 8; ks++) {
        qa[ks][0] = __float_as_uint(__uint_as_float(qbase[(size_t)lq       * 64 + ks * 8 + lr    ]) * 0.125f);
        qa[ks][1] = __float_as_uint(__uint_as_float(qbase[(size_t)(lq + 8) * 64 + ks * 8 + lr    ]) * 0.125f);
        qa[ks][2] = __float_as_uint(__uint_as_float(qbase[(size_t)lq       * 64 + ks * 8 + lr + 4]) * 0.125f);
        qa[ks][3] = __float_as_uint(__uint_as_float(qbase[(size_t)(lq + 8) * 64 + ks * 8 + lr + 4]) * 0.125f);
    }

    float o[8][4];
    #pragma unroll
    for (int nt = 0; nt < 8; nt++)
        #pragma unroll
        for (int e = 0; e < 4; e++) o[nt][e] = 0.f;
    float lsum0 = 0.f, lsum1 = 0.f;

    const uint32_t* kb = g_k + (size_t)bh * 512 * 64;
    const uint32_t* vb = g_v + (size_t)bh * 512 * 64;

    for (int kt = 0; kt < 8; kt++) {
        __syncthreads();
        #pragma unroll
        for (int i = 0; i < 4; i++) {
            int idx = tid + i * 256;
            int row = idx >> 4, c4 = (idx & 15) << 2;
            *(uint4*)(Ks + row * KSTR + c4) = *(const uint4*)(kb + (size_t)kt * 4096 + idx * 4);
            *(uint4*)(Vs + row * VSTR + c4) = *(const uint4*)(vb + (size_t)kt * 4096 + idx * 4);
        }
        __syncthreads();

        float sc[8][4];
        #pragma unroll
        for (int nt = 0; nt < 8; nt++) {
            sc[nt][0] = sc[nt][1] = sc[nt][2] = sc[nt][3] = 0.f;
            #pragma unroll
            for (int ks = 0; ks < 8; ks++) {
                uint32_t bf[2];
                bf[0] = Ks[(nt * 8 + lq) * KSTR + ks * 8 + lr    ];
                bf[1] = Ks[(nt * 8 + lq) * KSTR + ks * 8 + lr + 4];
                mma_tf32(sc[nt], qa[ks], bf);
            }
        }

        #pragma unroll
        for (int nt = 0; nt < 8; nt++) {
            float p0 = __expf(sc[nt][0]), p1 = __expf(sc[nt][1]);
            float p2 = __expf(sc[nt][2]), p3 = __expf(sc[nt][3]);
            sc[nt][0] = p0; sc[nt][1] = p1; sc[nt][2] = p2; sc[nt][3] = p3;
            lsum0 += p0 + p1;
            lsum1 += p2 + p3;
        }

        #pragma unroll
        for (int ks = 0; ks < 8; ks++) {
            int src  = (lane & ~3) | (lr >> 1);
            float t0 = __shfl_sync(0xffffffffu, sc[ks][0], src);
            float t1 = __shfl_sync(0xffffffffu, sc[ks][1], src);
            float t2 = __shfl_sync(0xffffffffu, sc[ks][2], src);
            float t3 = __shfl_sync(0xffffffffu, sc[ks][3], src);
            float u0 = __shfl_sync(0xffffffffu, sc[ks][0], src + 2);
            float u1 = __shfl_sync(0xffffffffu, sc[ks][1], src + 2);
            float u2 = __shfl_sync(0xffffffffu, sc[ks][2], src + 2);
            float u3 = __shfl_sync(0xffffffffu, sc[ks][3], src + 2);
            uint32_t pa[4];
            pa[0] = f2tf32((lr & 1) ? t1 : t0);
            pa[1] = f2tf32((lr & 1) ? t3 : t2);
            pa[2] = f2tf32((lr & 1) ? u1 : u0);
            pa[3] = f2tf32((lr & 1) ? u3 : u2);
            #pragma unroll
            for (int ntd = 0; ntd < 8; ntd++) {
                uint32_t bf[2];
                bf[0] = Vs[(ks * 8 + lr    ) * VSTR + ntd * 8 + lq];
                bf[1] = Vs[(ks * 8 + lr + 4) * VSTR + ntd * 8 + lq];
                mma_tf32(o[ntd], pa, bf);
            }
        }
    }

    lsum0 += __shfl_xor_sync(0xffffffffu, lsum0, 1);
    lsum0 += __shfl_xor_sync(0xffffffffu, lsum0, 2);
    lsum1 += __shfl_xor_sync(0xffffffffu, lsum1, 1);
    lsum1 += __shfl_xor_sync(0xffffffffu, lsum1, 2);
    const float inv0 = 1.f / lsum0;
    const float inv1 = 1.f / lsum1;

    const int bb = bh >> 4, h = bh & 15;
    const int qrow0 = qt * 128 + warp * 16 + lq;
    uint32_t* out0 = g_ctx + ((size_t)(bb * 512 + qrow0)) * 1024 + h * 64;
    uint32_t* out1 = out0 + (size_t)8 * 1024;
    #pragma unroll
    for (int ntd = 0; ntd < 8; ntd++) {
        uint2 v0 = { f2tf32(o[ntd][0] * inv0), f2tf32(o[ntd][1] * inv0) };
        uint2 v1 = { f2tf32(o[ntd][2] * inv1), f2tf32(o[ntd][3] * inv1) };
        *(uint2*)(out0 + ntd * 8 + 2 * lr) = v0;
        *(uint2*)(out1 + ntd * 8 + 2 * lr) = v1;
    }
}

// ---------------------------------------------------------------------------
// Kernel 3: output projection.  A (ctx) S20-staged raw tf32 (scalar LDS),
// B (Wo) fragment-ordered -> LDS.128.  3-stage cp.async, BK=16, 512 threads.
// ---------------------------------------------------------------------------
#define OP_ASTG (128 * S20)   // 2560 u32
#define OP_BSTG 2048          // u32 (8 pair-tiles x 2 ks x 128)
#define OP_SMEM ((3 * OP_ASTG + 3 * OP_BSTG) * 4)

__global__ __launch_bounds__(512)
void outproj_mma(const float* __restrict__ bo, float* __restrict__ out)
{
    extern __shared__ uint32_t sm[];
    uint32_t* As = sm;
    uint32_t* Bs = sm + 3 * OP_ASTG;

    const int tid  = threadIdx.x;
    const int warp = tid >> 5;
    const int lane = tid & 31;
    const int wm   = warp >> 2;
    const int wn   = warp & 3;
    const int m0   = blockIdx.x * 128;
    const int nb   = blockIdx.y;            // n0 = nb*128
    const int lq   = lane >> 2;
    const int lr   = lane & 3;

    const int arow = tid >> 2;
    const int ac4  = (tid & 3) * 4;
    const uint32_t* a_src = g_ctx + (size_t)(m0 + arow) * 1024 + ac4;
    uint32_t a_dst[3], b_dst[3];
    #pragma unroll
    for (int s = 0; s < 3; s++) {
        a_dst[s] = smem_u32(&As[s * OP_ASTG + arow * S20 + ac4]);
        b_dst[s] = smem_u32(&Bs[s * OP_BSTG + tid * 4]);
    }
    const uint32_t* b_base = g_wo + (size_t)nb * 64 * OP_BSTG;

    float acc[2][4][4];
    #pragma unroll
    for (int mt = 0; mt < 2; mt++)
        #pragma unroll
        for (int nt = 0; nt < 4; nt++)
            #pragma unroll
            for (int e = 0; e < 4; e++) acc[mt][nt][e] = 0.f;

    #pragma unroll
    for (int s = 0; s < 2; s++) {
        CP16(a_dst[s], a_src + s * 16);
        CP16(b_dst[s], b_base + s * OP_BSTG + tid * 4);
        CP_COMMIT();
    }

    for (int it = 0; it < 64; ++it) {
        CP_WAIT1();
        __syncthreads();

        if (it + 2 < 64) {
            int s = (it + 2) % 3;
            CP16(a_dst[s], a_src + (it + 2) * 16);
            CP16(b_dst[s], b_base + (size_t)(it + 2) * OP_BSTG + tid * 4);
        }
        CP_COMMIT();

        const uint32_t* Ac = As + (it % 3) * OP_ASTG;
        const uint32_t* Bc = Bs + (it % 3) * OP_BSTG;

        #pragma unroll
        for (int ks = 0; ks < 2; ks++) {
            uint32_t af[2][4];
            #pragma unroll
            for (int mt = 0; mt < 2; mt++) {
                int mb = wm * 32 + mt * 16;
                af[mt][0] = Ac[(mb +     lq) * S20 + ks * 8 + lr];
                af[mt][1] = Ac[(mb + 8 + lq) * S20 + ks * 8 + lr];
                af[mt][2] = Ac[(mb +     lq) * S20 + ks * 8 + lr + 4];
                af[mt][3] = Ac[(mb + 8 + lq) * S20 + ks * 8 + lr + 4];
            }
            #pragma unroll
            for (int pl = 0; pl < 2; pl++) {
                uint4 bv = *(const uint4*)&Bc[(ks * 8 + wn * 2 + pl) * 128 + lane * 4];
                uint32_t bfe[2] = { bv.x, bv.y };
                uint32_t bfo[2] = { bv.z, bv.w };
                mma_tf32(acc[0][2*pl  ], af[0], bfe);
                mma_tf32(acc[1][2*pl  ], af[1], bfe);
                mma_tf32(acc[0][2*pl+1], af[0], bfo);
                mma_tf32(acc[1][2*pl+1], af[1], bfo);
            }
        }
    }

    #pragma unroll
    for (int mt = 0; mt < 2; mt++) {
        #pragma unroll
        for (int half = 0; half < 2; half++) {
            int m = m0 + wm * 32 + mt * 16 + half * 8 + lq;
            float* rowp = out + (size_t)m * 1024 + nb * 128;
            #pragma unroll
            for (int nt = 0; nt < 4; nt++) {
                int n = wn * 32 + nt * 8 + 2 * lr;
                float2 v;
                v.x = acc[mt][nt][half * 2 + 0] + bo[nb * 128 + n];
                v.y = acc[mt][nt][half * 2 + 1] + bo[nb * 128 + n + 1];
                *(float2*)(rowp + n) = v;
            }
        }
    }
}

// ---------------------------------------------------------------------------
extern "C" void kernel_launch(void* const* d_in, const int* in_sizes, int n_in,
                              void* d_out, int out_size)
{
    const float* x  = (const float*)d_in[0];
    const float* Wq = (const float*)d_in[1];
    const float* bq = (const float*)d_in[2];
    const float* Wk = (const float*)d_in[3];
    const float* bk = (const float*)d_in[4];
    const float* Wv = (const float*)d_in[5];
    const float* bv = (const float*)d_in[6];
    const float* Wo = (const float*)d_in[7];
    const float* bo = (const float*)d_in[8];
    float* out = (float*)d_out;

    static bool attr_done = false;
    if (!attr_done) {
        cudaFuncSetAttribute(qkv_mma, cudaFuncAttributeMaxDynamicSharedMemorySize, QKV_SMEM);
        cudaFuncSetAttribute(outproj_mma, cudaFuncAttributeMaxDynamicSharedMemorySize, OP_SMEM);
        attr_done = true;
    }

    cvt_weights<<<256, 256>>>(Wq, Wk, Wv, Wo);

    qkv_mma<<<MQKV / 128, 512, QKV_SMEM>>>(x, bq, bk, bv);

    dim3 g2(BB_ * HH_, SP_ / 128);
    attn_mma<<<g2, 256>>>();

    dim3 g3(MOUT / 128, EE_ / 128);
    outproj_mma<<<g3, 512, OP_SMEM>>>(bo, out);
}

// round 10
// speedup vs baseline: 1.6358x; 1.0444x over previous
#include <cuda_runtime.h>
#include <stdint.h>

// Problem constants
#define BB_  4
#define SS_  8192
#define EE_  1024
#define HH_  16
#define DD_  64
#define SP_  512
#define MQKV (BB_*SS_)
#define MOUT (BB_*SP_)

// Scratch: q/k/v/ctx hold tf32 bit patterns; weights pre-converted AND
// pre-swizzled into mma-fragment order.
__device__ uint32_t g_q[BB_*HH_*SP_*DD_];     // [B,H,S',D] tf32 bits
__device__ uint32_t g_k[BB_*HH_*SP_*DD_];
__device__ uint32_t g_v[BB_*HH_*SP_*DD_];
__device__ uint32_t g_ctx[BB_*SP_*EE_];       // [B,S',E]  tf32 bits
__device__ uint32_t g_wqkv[192*EE_];          // fragment-ordered [Wq;Wk;Wv]
__device__ uint32_t g_wo[EE_*EE_];            // fragment-ordered Wo

// ---------------------------------------------------------------------------
// helpers
// ---------------------------------------------------------------------------
__device__ __forceinline__ uint32_t f2tf32(float f) {
    uint32_t u;
    asm("cvt.rna.tf32.f32 %0, %1;" : "=r"(u) : "f"(f));
    return u;
}

__device__ __forceinline__ void mma_tf32(float c[4], const uint32_t a[4], const uint32_t b[2]) {
    asm volatile(
        "mma.sync.aligned.m16n8k8.row.col.f32.tf32.tf32.f32 "
        "{%0,%1,%2,%3}, {%4,%5,%6,%7}, {%8,%9}, {%0,%1,%2,%3};\n"
        : "+f"(c[0]), "+f"(c[1]), "+f"(c[2]), "+f"(c[3])
        : "r"(a[0]), "r"(a[1]), "r"(a[2]), "r"(a[3]), "r"(b[0]), "r"(b[1]));
}

// ldmatrix x4: loads a full m16k8 tf32 A-fragment from row-major smem.
// Lane groups 0-7/8-15/16-23/24-31 provide row addresses for subtiles
// (m0-7,k0-3)/(m8-15,k0-3)/(m0-7,k4-7)/(m8-15,k4-7) -> regs r0..r3 match
// the tf32 A-fragment order exactly.
__device__ __forceinline__ void ldsm_x4(uint32_t r[4], uint32_t addr) {
    asm volatile("ldmatrix.sync.aligned.m8n8.x4.shared.b16 {%0,%1,%2,%3}, [%4];"
                 : "=r"(r[0]), "=r"(r[1]), "=r"(r[2]), "=r"(r[3]) : "r"(addr));
}

__device__ __forceinline__ uint32_t smem_u32(const void* p) {
    return (uint32_t)__cvta_generic_to_shared(p);
}
#define CP16(dst, src) asm volatile("cp.async.cg.shared.global [%0], [%1], 16;\n" :: "r"(dst), "l"(src))
#define CP_COMMIT()    asm volatile("cp.async.commit_group;\n" ::: "memory")
#define CP_WAIT1()     asm volatile("cp.async.wait_group 1;\n" ::: "memory")

#define S20 20   // smem row stride (80B): LDSM phases conflict-free, 16B-aligned

// Fragment-pair tile: 16 n-rows x 8 k, 128 u32.
__device__ __forceinline__ int frag_idx(int n16, int k8) {
    return ((n16 & 7) * 4 + (k8 & 3)) * 4 + ((n16 >> 3) << 1) + (k8 >> 2);
}

// ---------------------------------------------------------------------------
// Kernel 0: pre-convert + pre-swizzle weights (once per launch, ~5us)
// ---------------------------------------------------------------------------
__global__ __launch_bounds__(256)
void cvt_weights(const float* __restrict__ Wq, const float* __restrict__ Wk,
                 const float* __restrict__ Wv, const float* __restrict__ Wo)
{
    const int idx = blockIdx.x * 256 + threadIdx.x;   // 0..65535
    const int row = idx >> 10;
    const int k   = idx & 1023;
    const int it  = k >> 4;
    const int ks  = (k >> 3) & 1;
    const int k8  = k & 7;

    {
        const float* Ws[3] = { Wq, Wk, Wv };
        #pragma unroll
        for (int mat = 0; mat < 3; mat++) {
            int n = mat * 64 + row;
            int addr = ((it * 2 + ks) * 12 + (n >> 4)) * 128 + frag_idx(n & 15, k8);
            g_wqkv[addr] = f2tf32(Ws[mat][row * 1024 + k]);
        }
    }
    #pragma unroll
    for (int j = 0; j < 16; j++) {
        int e  = idx + j * 65536;
        int n  = e >> 10;
        int kk = e & 1023;
        int it2 = kk >> 4, ks2 = (kk >> 3) & 1, k82 = kk & 7;
        int nb = n >> 7, nn = n & 127;
        int addr = (((nb * 64 + it2) * 2 + ks2) * 8 + (nn >> 4)) * 128 + frag_idx(nn & 15, k82);
        g_wo[addr] = f2tf32(Wo[(size_t)n * 1024 + kk]);
    }
}

// ---------------------------------------------------------------------------
// Kernel 1: fused QKV projection.  A: row-major fp32 smem -> LDSM.x4 -> CVT.
// B: fragment-ordered tf32 -> LDS.128.  3-stage cp.async, BK=16, 512 thr.
// ---------------------------------------------------------------------------
#define QKV_ASTG (128 * S20)   // 2560 u32
#define QKV_BSTG 3072          // u32
#define QKV_SMEM ((3 * QKV_ASTG + 3 * QKV_BSTG) * 4)

__global__ __launch_bounds__(512)
void qkv_mma(const float* __restrict__ x,
             const float* __restrict__ bq, const float* __restrict__ bk,
             const float* __restrict__ bv)
{
    extern __shared__ uint32_t sm[];
    uint32_t* As = sm;                      // 3 stages of [128][S20]
    uint32_t* Bs = sm + 3 * QKV_ASTG;       // 3 stages of 3072 (fragment order)

    const int tid  = threadIdx.x;
    const int warp = tid >> 5;
    const int lane = tid & 31;
    const int wm   = warp >> 2;
    const int wn   = warp & 3;
    const int m0   = blockIdx.x * 128;
    const int lq   = lane >> 2;
    const int lr   = lane & 3;

    // LDSM per-lane address components
    const int lt       = lane >> 3;             // subtile group 0..3
    const int lrw      = lane & 7;
    const int arow_off = (lt & 1) * 8 + lrw;    // 0..15 within m16 tile
    const int akoff    = (lt >> 1) * 4;         // 0 or 4 (tf32 cols)
    uint32_t a_ldsm[3];
    #pragma unroll
    for (int s = 0; s < 3; s++)
        a_ldsm[s] = smem_u32(&As[s * QKV_ASTG + (wm * 32 + arow_off) * S20 + akoff]);

    // A tile loads: 128x16 = 512 float4, 1 per thread
    const int arow = tid >> 2;
    const int ac4  = (tid & 3) * 4;
    const float* a_src = x + (size_t)(m0 + arow) * 1024 + ac4;
    uint32_t a_dst[3];
    #pragma unroll
    for (int s = 0; s < 3; s++)
        a_dst[s] = smem_u32(&As[s * QKV_ASTG + arow * S20 + ac4]);

    // B tile: 3072 u32 = 768 16B-chunks
    const bool has2 = (tid < 256);
    uint32_t b_dst1[3], b_dst2[3];
    #pragma unroll
    for (int s = 0; s < 3; s++) {
        b_dst1[s] = smem_u32(&Bs[s * QKV_BSTG + tid * 4]);
        b_dst2[s] = smem_u32(&Bs[s * QKV_BSTG + (512 + tid) * 4]);
    }

    float acc[2][6][4];
    #pragma unroll
    for (int mt = 0; mt < 2; mt++)
        #pragma unroll
        for (int nt = 0; nt < 6; nt++)
            #pragma unroll
            for (int e = 0; e < 4; e++) acc[mt][nt][e] = 0.f;

    #pragma unroll
    for (int s = 0; s < 2; s++) {
        CP16(a_dst[s], a_src + s * 16);
        CP16(b_dst1[s], g_wqkv + s * QKV_BSTG + tid * 4);
        if (has2) CP16(b_dst2[s], g_wqkv + s * QKV_BSTG + (512 + tid) * 4);
        CP_COMMIT();
    }

    for (int it = 0; it < 64; ++it) {
        CP_WAIT1();
        __syncthreads();

        if (it + 2 < 64) {
            int s = (it + 2) % 3;
            CP16(a_dst[s], a_src + (it + 2) * 16);
            CP16(b_dst1[s], g_wqkv + (it + 2) * QKV_BSTG + tid * 4);
            if (has2) CP16(b_dst2[s], g_wqkv + (it + 2) * QKV_BSTG + (512 + tid) * 4);
        }
        CP_COMMIT();

        const int cur = it % 3;
        const uint32_t* Bc = Bs + cur * QKV_BSTG;
        const uint32_t  Ab = a_ldsm[cur];

        #pragma unroll
        for (int ks = 0; ks < 2; ks++) {
            uint32_t af[2][4];
            #pragma unroll
            for (int mt = 0; mt < 2; mt++) {
                uint32_t raw[4];
                ldsm_x4(raw, Ab + (uint32_t)((mt * 16 * S20 + ks * 8) * 4));
                af[mt][0] = f2tf32(__uint_as_float(raw[0]));
                af[mt][1] = f2tf32(__uint_as_float(raw[1]));
                af[mt][2] = f2tf32(__uint_as_float(raw[2]));
                af[mt][3] = f2tf32(__uint_as_float(raw[3]));
            }
            #pragma unroll
            for (int pl = 0; pl < 3; pl++) {
                uint4 bv = *(const uint4*)&Bc[(ks * 12 + wn * 3 + pl) * 128 + lane * 4];
                uint32_t bfe[2] = { bv.x, bv.y };
                uint32_t bfo[2] = { bv.z, bv.w };
                mma_tf32(acc[0][2*pl  ], af[0], bfe);
                mma_tf32(acc[1][2*pl  ], af[1], bfe);
                mma_tf32(acc[0][2*pl+1], af[0], bfo);
                mma_tf32(acc[1][2*pl+1], af[1], bfo);
            }
        }
    }

    // Epilogue: bias + scatter into [B,H,S',D] as tf32 bits
    #pragma unroll
    for (int mt = 0; mt < 2; mt++) {
        #pragma unroll
        for (int half = 0; half < 2; half++) {
            int m  = m0 + wm * 32 + mt * 16 + half * 8 + lq;
            int bb = m >> 13;
            int s  = m & 8191;
            int sp = s >> 4;
            int h  = s & 15;
            size_t rowoff = ((size_t)(bb * 16 + h) * 512 + sp) * 64;
            #pragma unroll
            for (int nt = 0; nt < 6; nt++) {
                int n   = wn * 48 + nt * 8 + 2 * lr;
                int mat = n >> 6;
                int nn  = n & 63;
                uint32_t* dst = (mat == 0) ? g_q : (mat == 1 ? g_k : g_v);
                const float* bias = (mat == 0) ? bq : (mat == 1 ? bk : bv);
                uint2 v;
                v.x = f2tf32(acc[mt][nt][half * 2 + 0] + bias[nn]);
                v.y = f2tf32(acc[mt][nt][half * 2 + 1] + bias[nn + 1]);
                *(uint2*)(dst + rowoff + nn) = v;
            }
        }
    }
}

// ---------------------------------------------------------------------------
// Kernel 2: attention (unchanged — tf32 bits in, tf32 bits out).
// ---------------------------------------------------------------------------
#define KSTR 68
#define VSTR 72

__global__ __launch_bounds__(256)
void attn_mma()
{
    __shared__ uint32_t Ks[64 * KSTR];
    __shared__ uint32_t Vs[64 * VSTR];

    const int bh   = blockIdx.x;
    const int qt   = blockIdx.y;
    const int tid  = threadIdx.x;
    const int warp = tid >> 5;
    const int lane = tid & 31;
    const int lq   = lane >> 2;
    const int lr   = lane & 3;

    const uint32_t* qbase = g_q + ((size_t)bh * 512 + qt * 128 + warp * 16) * 64;
    uint32_t qa[8][4];
    #pragma unroll
    for (int ks = 0; ks < 8; ks++) {
        qa[ks][0] = __float_as_uint(__uint_as_float(qbase[(size_t)lq       * 64 + ks * 8 + lr    ]) * 0.125f);
        qa[ks][1] = __float_as_uint(__uint_as_float(qbase[(size_t)(lq + 8) * 64 + ks * 8 + lr    ]) * 0.125f);
        qa[ks][2] = __float_as_uint(__uint_as_float(qbase[(size_t)lq       * 64 + ks * 8 + lr + 4]) * 0.125f);
        qa[ks][3] = __float_as_uint(__uint_as_float(qbase[(size_t)(lq + 8) * 64 + ks * 8 + lr + 4]) * 0.125f);
    }

    float o[8][4];
    #pragma unroll
    for (int nt = 0; nt < 8; nt++)
        #pragma unroll
        for (int e = 0; e < 4; e++) o[nt][e] = 0.f;
    float lsum0 = 0.f, lsum1 = 0.f;

    const uint32_t* kb = g_k + (size_t)bh * 512 * 64;
    const uint32_t* vb = g_v + (size_t)bh * 512 * 64;

    for (int kt = 0; kt < 8; kt++) {
        __syncthreads();
        #pragma unroll
        for (int i = 0; i < 4; i++) {
            int idx = tid + i * 256;
            int row = idx >> 4, c4 = (idx & 15) << 2;
            *(uint4*)(Ks + row * KSTR + c4) = *(const uint4*)(kb + (size_t)kt * 4096 + idx * 4);
            *(uint4*)(Vs + row * VSTR + c4) = *(const uint4*)(vb + (size_t)kt * 4096 + idx * 4);
        }
        __syncthreads();

        float sc[8][4];
        #pragma unroll
        for (int nt = 0; nt < 8; nt++) {
            sc[nt][0] = sc[nt][1] = sc[nt][2] = sc[nt][3] = 0.f;
            #pragma unroll
            for (int ks = 0; ks < 8; ks++) {
                uint32_t bf[2];
                bf[0] = Ks[(nt * 8 + lq) * KSTR + ks * 8 + lr    ];
                bf[1] = Ks[(nt * 8 + lq) * KSTR + ks * 8 + lr + 4];
                mma_tf32(sc[nt], qa[ks], bf);
            }
        }

        #pragma unroll
        for (int nt = 0; nt < 8; nt++) {
            float p0 = __expf(sc[nt][0]), p1 = __expf(sc[nt][1]);
            float p2 = __expf(sc[nt][2]), p3 = __expf(sc[nt][3]);
            sc[nt][0] = p0; sc[nt][1] = p1; sc[nt][2] = p2; sc[nt][3] = p3;
            lsum0 += p0 + p1;
            lsum1 += p2 + p3;
        }

        #pragma unroll
        for (int ks = 0; ks < 8; ks++) {
            int src  = (lane & ~3) | (lr >> 1);
            float t0 = __shfl_sync(0xffffffffu, sc[ks][0], src);
            float t1 = __shfl_sync(0xffffffffu, sc[ks][1], src);
            float t2 = __shfl_sync(0xffffffffu, sc[ks][2], src);
            float t3 = __shfl_sync(0xffffffffu, sc[ks][3], src);
            float u0 = __shfl_sync(0xffffffffu, sc[ks][0], src + 2);
            float u1 = __shfl_sync(0xffffffffu, sc[ks][1], src + 2);
            float u2 = __shfl_sync(0xffffffffu, sc[ks][2], src + 2);
            float u3 = __shfl_sync(0xffffffffu, sc[ks][3], src + 2);
            uint32_t pa[4];
            pa[0] = f2tf32((lr & 1) ? t1 : t0);
            pa[1] = f2tf32((lr & 1) ? t3 : t2);
            pa[2] = f2tf32((lr & 1) ? u1 : u0);
            pa[3] = f2tf32((lr & 1) ? u3 : u2);
            #pragma unroll
            for (int ntd = 0; ntd < 8; ntd++) {
                uint32_t bf[2];
                bf[0] = Vs[(ks * 8 + lr    ) * VSTR + ntd * 8 + lq];
                bf[1] = Vs[(ks * 8 + lr + 4) * VSTR + ntd * 8 + lq];
                mma_tf32(o[ntd], pa, bf);
            }
        }
    }

    lsum0 += __shfl_xor_sync(0xffffffffu, lsum0, 1);
    lsum0 += __shfl_xor_sync(0xffffffffu, lsum0, 2);
    lsum1 += __shfl_xor_sync(0xffffffffu, lsum1, 1);
    lsum1 += __shfl_xor_sync(0xffffffffu, lsum1, 2);
    const float inv0 = 1.f / lsum0;
    const float inv1 = 1.f / lsum1;

    const int bb = bh >> 4, h = bh & 15;
    const int qrow0 = qt * 128 + warp * 16 + lq;
    uint32_t* out0 = g_ctx + ((size_t)(bb * 512 + qrow0)) * 1024 + h * 64;
    uint32_t* out1 = out0 + (size_t)8 * 1024;
    #pragma unroll
    for (int ntd = 0; ntd < 8; ntd++) {
        uint2 v0 = { f2tf32(o[ntd][0] * inv0), f2tf32(o[ntd][1] * inv0) };
        uint2 v1 = { f2tf32(o[ntd][2] * inv1), f2tf32(o[ntd][3] * inv1) };
        *(uint2*)(out0 + ntd * 8 + 2 * lr) = v0;
        *(uint2*)(out1 + ntd * 8 + 2 * lr) = v1;
    }
}

// ---------------------------------------------------------------------------
// Kernel 3: output projection.  A (ctx, tf32 bits) -> LDSM.x4, no CVT.
// B (Wo) fragment-ordered -> LDS.128.  3-stage cp.async, BK=16, 512 threads.
// ---------------------------------------------------------------------------
#define OP_ASTG (128 * S20)   // 2560 u32
#define OP_BSTG 2048          // u32
#define OP_SMEM ((3 * OP_ASTG + 3 * OP_BSTG) * 4)

__global__ __launch_bounds__(512)
void outproj_mma(const float* __restrict__ bo, float* __restrict__ out)
{
    extern __shared__ uint32_t sm[];
    uint32_t* As = sm;
    uint32_t* Bs = sm + 3 * OP_ASTG;

    const int tid  = threadIdx.x;
    const int warp = tid >> 5;
    const int lane = tid & 31;
    const int wm   = warp >> 2;
    const int wn   = warp & 3;
    const int m0   = blockIdx.x * 128;
    const int nb   = blockIdx.y;
    const int lq   = lane >> 2;
    const int lr   = lane & 3;

    const int lt       = lane >> 3;
    const int lrw      = lane & 7;
    const int arow_off = (lt & 1) * 8 + lrw;
    const int akoff    = (lt >> 1) * 4;
    uint32_t a_ldsm[3];
    #pragma unroll
    for (int s = 0; s < 3; s++)
        a_ldsm[s] = smem_u32(&As[s * OP_ASTG + (wm * 32 + arow_off) * S20 + akoff]);

    const int arow = tid >> 2;
    const int ac4  = (tid & 3) * 4;
    const uint32_t* a_src = g_ctx + (size_t)(m0 + arow) * 1024 + ac4;
    uint32_t a_dst[3], b_dst[3];
    #pragma unroll
    for (int s = 0; s < 3; s++) {
        a_dst[s] = smem_u32(&As[s * OP_ASTG + arow * S20 + ac4]);
        b_dst[s] = smem_u32(&Bs[s * OP_BSTG + tid * 4]);
    }
    const uint32_t* b_base = g_wo + (size_t)nb * 64 * OP_BSTG;

    float acc[2][4][4];
    #pragma unroll
    for (int mt = 0; mt < 2; mt++)
        #pragma unroll
        for (int nt = 0; nt < 4; nt++)
            #pragma unroll
            for (int e = 0; e < 4; e++) acc[mt][nt][e] = 0.f;

    #pragma unroll
    for (int s = 0; s < 2; s++) {
        CP16(a_dst[s], a_src + s * 16);
        CP16(b_dst[s], b_base + s * OP_BSTG + tid * 4);
        CP_COMMIT();
    }

    for (int it = 0; it < 64; ++it) {
        CP_WAIT1();
        __syncthreads();

        if (it + 2 < 64) {
            int s = (it + 2) % 3;
            CP16(a_dst[s], a_src + (it + 2) * 16);
            CP16(b_dst[s], b_base + (size_t)(it + 2) * OP_BSTG + tid * 4);
        }
        CP_COMMIT();

        const int cur = it % 3;
        const uint32_t* Bc = Bs + cur * OP_BSTG;
        const uint32_t  Ab = a_ldsm[cur];

        #pragma unroll
        for (int ks = 0; ks < 2; ks++) {
            uint32_t af[2][4];
            #pragma unroll
            for (int mt = 0; mt < 2; mt++)
                ldsm_x4(af[mt], Ab + (uint32_t)((mt * 16 * S20 + ks * 8) * 4));
            #pragma unroll
            for (int pl = 0; pl < 2; pl++) {
                uint4 bv = *(const uint4*)&Bc[(ks * 8 + wn * 2 + pl) * 128 + lane * 4];
                uint32_t bfe[2] = { bv.x, bv.y };
                uint32_t bfo[2] = { bv.z, bv.w };
                mma_tf32(acc[0][2*pl  ], af[0], bfe);
                mma_tf32(acc[1][2*pl  ], af[1], bfe);
                mma_tf32(acc[0][2*pl+1], af[0], bfo);
                mma_tf32(acc[1][2*pl+1], af[1], bfo);
            }
        }
    }

    #pragma unroll
    for (int mt = 0; mt < 2; mt++) {
        #pragma unroll
        for (int half = 0; half < 2; half++) {
            int m = m0 + wm * 32 + mt * 16 + half * 8 + lq;
            float* rowp = out + (size_t)m * 1024 + nb * 128;
            #pragma unroll
            for (int nt = 0; nt < 4; nt++) {
                int n = wn * 32 + nt * 8 + 2 * lr;
                float2 v;
                v.x = acc[mt][nt][half * 2 + 0] + bo[nb * 128 + n];
                v.y = acc[mt][nt][half * 2 + 1] + bo[nb * 128 + n + 1];
                *(float2*)(rowp + n) = v;
            }
        }
    }
}

// ---------------------------------------------------------------------------
extern "C" void kernel_launch(void* const* d_in, const int* in_sizes, int n_in,
                              void* d_out, int out_size)
{
    const float* x  = (const float*)d_in[0];
    const float* Wq = (const float*)d_in[1];
    const float* bq = (const float*)d_in[2];
    const float* Wk = (const float*)d_in[3];
    const float* bk = (const float*)d_in[4];
    const float* Wv = (const float*)d_in[5];
    const float* bv = (const float*)d_in[6];
    const float* Wo = (const float*)d_in[7];
    const float* bo = (const float*)d_in[8];
    float* out = (float*)d_out;

    static bool attr_done = false;
    if (!attr_done) {
        cudaFuncSetAttribute(qkv_mma, cudaFuncAttributeMaxDynamicSharedMemorySize, QKV_SMEM);
        cudaFuncSetAttribute(outproj_mma, cudaFuncAttributeMaxDynamicSharedMemorySize, OP_SMEM);
        attr_done = true;
    }

    cvt_weights<<<256, 256>>>(Wq, Wk, Wv, Wo);

    qkv_mma<<<MQKV / 128, 512, QKV_SMEM>>>(x, bq, bk, bv);

    dim3 g2(BB_ * HH_, SP_ / 128);
    attn_mma<<<g2, 256>>>();

    dim3 g3(MOUT / 128, EE_ / 128);
    outproj_mma<<<g3, 512, OP_SMEM>>>(bo, out);
}